// round 5
// baseline (speedup 1.0000x reference)
#include <cuda_runtime.h>
#include <math.h>

typedef unsigned long long ull;
struct __align__(16) ULL2 { ull x, y; };

#define B_     64
#define F_     4097
#define FCL_   65
#define FL_    64
#define OUT_S  262144
#define NFRB   32          // owned frames per block
#define NSLOT  34          // + 2 halo frames (f0-2, f0-1)
#define NWARP  8

// ---------------- packed f32x2 helpers (Blackwell FFMA2 path) ----------------
__device__ __forceinline__ ull fma2_(ull a, ull b, ull c) {
    ull d; asm("fma.rn.f32x2 %0,%1,%2,%3;" : "=l"(d) : "l"(a), "l"(b), "l"(c)); return d;
}
__device__ __forceinline__ ull add2_(ull a, ull b) {
    ull d; asm("add.rn.f32x2 %0,%1,%2;" : "=l"(d) : "l"(a), "l"(b)); return d;
}
__device__ __forceinline__ ull mul2_(ull a, ull b) {
    ull d; asm("mul.rn.f32x2 %0,%1,%2;" : "=l"(d) : "l"(a), "l"(b)); return d;
}
__device__ __forceinline__ ull dup_(float x) {
    ull d; unsigned r = __float_as_uint(x);
    asm("mov.b64 %0,{%1,%1};" : "=l"(d) : "r"(r)); return d;
}
__device__ __forceinline__ ull pk_(float lo, float hi) {
    ull d; asm("mov.b64 %0,{%1,%2};" : "=l"(d) : "r"(__float_as_uint(lo)), "r"(__float_as_uint(hi))); return d;
}
__device__ __forceinline__ void unpk_(ull v, float& lo, float& hi) {
    unsigned a, b; asm("mov.b64 {%0,%1},%2;" : "=r"(a), "=r"(b) : "l"(v));
    lo = __uint_as_float(a); hi = __uint_as_float(b);
}

// ---------------- trig tables: integer mod-129 reduction + fp32 cosf ----------------
__device__ float2 g_cosP[64 * 32];   // [k-1][l] = (cos(th*k*(l+1)), cos(th*k*(l+33)))
__device__ float  g_win[130];

__global__ void init_tables_k() {
    int i = blockIdx.x * blockDim.x + threadIdx.x;
    const float TH = 6.283185307179586477f / 129.0f;
    if (i < 64 * 32) {
        int k = (i >> 5) + 1, l = i & 31;
        int m1 = (k * (l + 1))  % 129;
        int m2 = (k * (l + 33)) % 129;
        g_cosP[i] = make_float2(cosf(TH * (float)m1), cosf(TH * (float)m2));
    }
    if (i < 130) g_win[i] = 0.5f - 0.5f * cosf(TH * (float)i);
}

__device__ __forceinline__ float msig(float x) {
    float sg = 1.0f / (1.0f + __expf(-x));
    return 2.0f * __powf(sg, 2.302585092994046f) + 1e-7f;
}

// ---------------- dynamic smem layout (bytes) ----------------
#define COS_OFF    0        // float2[64*32]     = 16384
#define WIN_OFF    16384    // float[130] pad    = 528
#define SINTJ_OFF  16912    // float[8][65][4]   = 8320
#define SHALO_OFF  25232    // float[2][65] pad  = 528
#define XSB_OFF    25760    // float[8][4][64]   = 8192
#define XHALO_OFF  33952    // float[2][64]      = 512
#define WIR_OFF    34464    // float[8][256]     = 8192
#define OUTB_OFF   42656    // float[34][192]    = 26112
#define SMEM_TOT   68768    // 67.2 KB -> 3 blocks/SM

// ---- one frame's windowed-IR build + 64x192 linear conv (one warp) ----
__device__ __forceinline__ void conv_frame(
        float* __restrict__ wb, const float* __restrict__ xs,
        float* __restrict__ orow, int l, int t1, int t2,
        float zp0, float zp1, float zp2,
        float w1p, float w1m, float w2p, float w2m, float wc)
{
    // windowed linear-phase IR: wb[128 +/- t] = win * zp (zp even-symmetric)
    wb[128 + t1] = w1p * zp1;
    wb[128 - t1] = w1m * zp1;
    wb[128 + t2] = w2p * zp2;
    wb[128 - t2] = w2m * zp2;
    if (l == 0) wb[128] = wc * zp0;
    __syncwarp();

    // out[t] = sum_tau x[tau] * wb[64+t-tau], t = 8*l + c (24 lanes x 8 outputs)
    const int ll = (l < 24) ? l : 0;
    ull acc0 = 0, acc1 = 0, acc2 = 0, acc3 = 0;
    const float* wp0 = wb + 60 + 8 * ll;         // 16B aligned
    ULL2 va = *(const ULL2*)(wp0);
    ULL2 vb = *(const ULL2*)(wp0 + 4);
    ULL2 vc = *(const ULL2*)(wp0 + 8);
    ull E0 = va.x, E1 = va.y, E2 = vb.x, E3 = vb.y, E4 = vc.x, E5 = vc.y;
    float f0v, f1v, f2v, f3v, f4v, f5v, f6v, f7v, f8v, f9v, f10v, f11v;
    unpk_(E0, f0v, f1v); unpk_(E1, f2v, f3v); unpk_(E2, f4v, f5v);
    unpk_(E3, f6v, f7v); unpk_(E4, f8v, f9v); unpk_(E5, f10v, f11v);
    ull O0 = pk_(f1v, f2v), O1 = pk_(f3v, f4v), O2 = pk_(f5v, f6v);
    ull O3 = pk_(f7v, f8v), O4 = pk_(f9v, f10v);
    float carry = f0v;

    #pragma unroll
    for (int g = 0; g < 16; g++) {
        const float4 xq = *(const float4*)(xs + 4 * g);
        const ull x0 = dup_(xq.x), x1 = dup_(xq.y), x2 = dup_(xq.z), x3 = dup_(xq.w);
        acc0 = fma2_(x0, E2, acc0); acc1 = fma2_(x0, E3, acc1);
        acc2 = fma2_(x0, E4, acc2); acc3 = fma2_(x0, E5, acc3);
        acc0 = fma2_(x1, O1, acc0); acc1 = fma2_(x1, O2, acc1);
        acc2 = fma2_(x1, O3, acc2); acc3 = fma2_(x1, O4, acc3);
        acc0 = fma2_(x2, E1, acc0); acc1 = fma2_(x2, E2, acc1);
        acc2 = fma2_(x2, E3, acc2); acc3 = fma2_(x2, E4, acc3);
        acc0 = fma2_(x3, O0, acc0); acc1 = fma2_(x3, O1, acc1);
        acc2 = fma2_(x3, O2, acc2); acc3 = fma2_(x3, O3, acc3);
        if (g < 15) {
            const ULL2 nw = *(const ULL2*)(wp0 - 4 * (g + 1));
            float nf0, nf1, nf2, nf3;
            unpk_(nw.x, nf0, nf1); unpk_(nw.y, nf2, nf3);
            E5 = E3; E4 = E2; E3 = E1; E2 = E0; E1 = nw.y; E0 = nw.x;
            O4 = O2; O3 = O1; O2 = O0; O1 = pk_(nf3, carry); O0 = pk_(nf1, nf2);
            carry = nf0;
        }
    }
    if (l < 24) {
        ULL2* op = (ULL2*)(orow + 8 * l);
        op[0] = ULL2{acc0, acc1};
        op[1] = ULL2{acc2, acc3};
    }
    __syncwarp();   // wb reused by next frame
}

__global__ __launch_bounds__(256) void fn_main(
        const float* __restrict__ coeff,   // (B, F, 65)
        const float* __restrict__ noise,   // (B, F, 64)
        float* __restrict__ out)           // (B, 262144)
{
    extern __shared__ __align__(16) char smdyn[];
    float2* cosP  = (float2*)(smdyn + COS_OFF);
    float*  winS  = (float*)(smdyn + WIN_OFF);
    float*  sIntJ = (float*)(smdyn + SINTJ_OFF);  // [w][k][ff]
    float*  sHalo = (float*)(smdyn + SHALO_OFF);  // [2][65]
    float*  xsb   = (float*)(smdyn + XSB_OFF);    // [w][ff][64]
    float*  xHalo = (float*)(smdyn + XHALO_OFF);  // [2][64]
    float*  wirb  = (float*)(smdyn + WIR_OFF);    // [w][256], zero outside [64,192]
    float*  outb  = (float*)(smdyn + OUTB_OFF);   // [slot][192]; slot = f - f0 + 2

    const int tid = threadIdx.x;
    const int w   = tid >> 5;
    const int l   = tid & 31;
    const int q   = blockIdx.x;          // 0..127
    const int b   = blockIdx.y;
    const int f0  = q * NFRB;

    // ---- stage tables, zero wir pads, stage inputs (msig / rescale) ----
    for (int i = tid; i < 64 * 32; i += 256) cosP[i] = g_cosP[i];
    for (int i = tid; i < 130;     i += 256) winS[i] = g_win[i];
    for (int i = tid; i < NWARP * 256; i += 256) wirb[i] = 0.f;
    if (q == 0) for (int i = tid; i < 2 * 192; i += 256) outb[i] = 0.f;

    const long long cb = ((long long)b * F_ + (f0 - 2)) * FCL_;
    for (int e = tid; e < NSLOT * FCL_; e += 256) {
        const int slot = e / 65, k = e - slot * 65;
        if (q == 0 && slot < 2) continue;
        const float v = msig(coeff[cb + e]);
        if (slot >= 2) {
            const int fi = slot - 2;
            sIntJ[(((fi & 7) * 65) + k) * 4 + (fi >> 3)] = v;
        } else {
            sHalo[slot * 65 + k] = v;
        }
    }
    const long long nb = ((long long)b * F_ + (f0 - 2)) * FL_;
    for (int e = tid; e < NSLOT * FL_; e += 256) {
        const int slot = e >> 6, t = e & 63;
        if (q == 0 && slot < 2) continue;
        const float v = 2.f * noise[nb + e] - 1.f;
        if (slot >= 2) {
            const int fi = slot - 2;
            xsb[((fi & 7) * 4 + (fi >> 3)) * 64 + t] = v;
        } else {
            xHalo[slot * 64 + t] = v;
        }
    }
    __syncthreads();

    // ---- per-lane constants ----
    const int   t1  = l + 1,  t2 = l + 33;
    const float w1p = winS[64 + t1], w1m = winS[64 - t1];
    const float w2p = winS[64 + t2], w2m = winS[64 - t2];
    const float wc  = winS[64];
    float* wb = wirb + w * 256;

    // ---- cosine transform, 4 owned frames per warp jointly (packed f32x2) ----
    // zp[t] = (s0 + 2*sum_{k=1..64} s_k cos(2pi k t/129)) / 129 ; lane: t1, t2
    const float* sw = sIntJ + w * 65 * 4;
    ull ac0AB = 0, ac0CD = 0, ac1AB = 0, ac1CD = 0, ac2AB = 0, ac2CD = 0;
    const ULL2 s0p = *(const ULL2*)sw;
    #pragma unroll 8
    for (int k = 1; k <= 64; k++) {
        const float2 ct = cosP[(k - 1) * 32 + l];
        const ULL2 sp = *(const ULL2*)(sw + k * 4);
        const ull c1d = dup_(ct.x), c2d = dup_(ct.y);
        ac1AB = fma2_(sp.x, c1d, ac1AB);  ac1CD = fma2_(sp.y, c1d, ac1CD);
        ac2AB = fma2_(sp.x, c2d, ac2AB);  ac2CD = fma2_(sp.y, c2d, ac2CD);
        ac0AB = add2_(ac0AB, sp.x);       ac0CD = add2_(ac0CD, sp.y);
    }
    const ull TWO = dup_(2.0f), SCL = dup_(1.0f / 129.0f);
    float zp0s[4], zp1s[4], zp2s[4];
    {
        ull r;
        r = mul2_(fma2_(ac0AB, TWO, s0p.x), SCL); unpk_(r, zp0s[0], zp0s[1]);
        r = mul2_(fma2_(ac0CD, TWO, s0p.y), SCL); unpk_(r, zp0s[2], zp0s[3]);
        r = mul2_(fma2_(ac1AB, TWO, s0p.x), SCL); unpk_(r, zp1s[0], zp1s[1]);
        r = mul2_(fma2_(ac1CD, TWO, s0p.y), SCL); unpk_(r, zp1s[2], zp1s[3]);
        r = mul2_(fma2_(ac2AB, TWO, s0p.x), SCL); unpk_(r, zp2s[0], zp2s[1]);
        r = mul2_(fma2_(ac2CD, TWO, s0p.y), SCL); unpk_(r, zp2s[2], zp2s[3]);
    }

    // ---- conv for the 4 owned frames ----
    #pragma unroll
    for (int ff = 0; ff < 4; ff++) {
        const int fi = ff * NWARP + w;
        conv_frame(wb, xsb + (w * 4 + ff) * 64, outb + (fi + 2) * 192,
                   l, t1, t2, zp0s[ff], zp1s[ff], zp2s[ff],
                   w1p, w1m, w2p, w2m, wc);
    }

    // ---- halo frames (slots 0,1 = f0-2, f0-1) on warps 0,1 ----
    if (w < 2 && q != 0) {
        const float* sh = sHalo + w * 65;
        float ac0 = 0.f, ac1 = 0.f, ac2 = 0.f;
        const float s0v = sh[0];
        #pragma unroll 8
        for (int k = 1; k <= 64; k++) {
            const float2 ct = cosP[(k - 1) * 32 + l];
            const float sk = sh[k];
            ac0 += sk;
            ac1 += sk * ct.x;
            ac2 += sk * ct.y;
        }
        const float SC = 1.0f / 129.0f;
        conv_frame(wb, xHalo + w * 64, outb + w * 192, l, t1, t2,
                   (s0v + 2.f * ac0) * SC, (s0v + 2.f * ac1) * SC,
                   (s0v + 2.f * ac2) * SC, w1p, w1m, w2p, w2m, wc);
    }

    __syncthreads();

    // ---- overlap-add: this block owns out[gb, gb+2048) exclusively ----
    const size_t rowb = (size_t)b * OUT_S + (size_t)q * 2048;
    #pragma unroll
    for (int p4 = tid; p4 < 512; p4 += 256) {
        const int p   = 4 * p4;
        const int fhi = p >> 6;
        const int t0  = p & 63;
        const float4 a = *(const float4*)(outb + (fhi + 2) * 192 + t0);
        const float4 bq = *(const float4*)(outb + (fhi + 1) * 192 + t0 + 64);
        const float4 c = *(const float4*)(outb + fhi * 192 + t0 + 128);
        float4 v;
        v.x = a.x + bq.x + c.x;
        v.y = a.y + bq.y + c.y;
        v.z = a.z + bq.z + c.z;
        v.w = a.w + bq.w + c.w;
        *(float4*)(out + rowb + p) = v;
    }
}

extern "C" void kernel_launch(void* const* d_in, const int* in_sizes, int n_in,
                              void* d_out, int out_size) {
    const float* coeff = (const float*)d_in[0];
    const float* noise = (const float*)d_in[1];
    float* out = (float*)d_out;

    cudaFuncSetAttribute(fn_main, cudaFuncAttributeMaxDynamicSharedMemorySize, SMEM_TOT);
    init_tables_k<<<17, 128>>>();
    dim3 grid(128, B_);
    fn_main<<<grid, 256, SMEM_TOT>>>(coeff, noise, out);
}

// round 6
// speedup vs baseline: 1.1549x; 1.1549x over previous
#include <cuda_runtime.h>
#include <math.h>

typedef unsigned long long ull;
struct __align__(16) ULL2 { ull x, y; };

#define B_     64
#define F_     4097
#define FCL_   65
#define FL_    64
#define OUT_S  262144
#define NFRB   32          // frames per block
#define NWARP  8
#define ACCLEN 2176        // (NFRB-1)*64 + 192

// ---------------- packed f32x2 helpers ----------------
__device__ __forceinline__ ull fma2_(ull a, ull b, ull c) {
    ull d; asm("fma.rn.f32x2 %0,%1,%2,%3;" : "=l"(d) : "l"(a), "l"(b), "l"(c)); return d;
}
__device__ __forceinline__ ull add2_(ull a, ull b) {
    ull d; asm("add.rn.f32x2 %0,%1,%2;" : "=l"(d) : "l"(a), "l"(b)); return d;
}
__device__ __forceinline__ ull mul2_(ull a, ull b) {
    ull d; asm("mul.rn.f32x2 %0,%1,%2;" : "=l"(d) : "l"(a), "l"(b)); return d;
}
__device__ __forceinline__ ull dup_(float x) {
    ull d; unsigned r = __float_as_uint(x);
    asm("mov.b64 %0,{%1,%1};" : "=l"(d) : "r"(r)); return d;
}
__device__ __forceinline__ ull pk_(float lo, float hi) {
    ull d; asm("mov.b64 %0,{%1,%2};" : "=l"(d) : "r"(__float_as_uint(lo)), "r"(__float_as_uint(hi))); return d;
}
__device__ __forceinline__ void unpk_(ull v, float& lo, float& hi) {
    unsigned a, b; asm("mov.b64 {%0,%1},%2;" : "=r"(a), "=r"(b) : "l"(v));
    lo = __uint_as_float(a); hi = __uint_as_float(b);
}

// ---------------- trig tables (L1-cached via __ldg; int mod-129 reduction) ----------------
__device__ float2 g_cosP[64 * 32];   // [k-1][l] = (cos(th*k*(l+1)), cos(th*k*(l+33)))
__device__ float  g_win[130];

__global__ void init_tables_k() {
    int i = blockIdx.x * blockDim.x + threadIdx.x;
    const float TH = 6.283185307179586477f / 129.0f;
    if (i < 64 * 32) {
        int k = (i >> 5) + 1, l = i & 31;
        int m1 = (k * (l + 1))  % 129;
        int m2 = (k * (l + 33)) % 129;
        g_cosP[i] = make_float2(cosf(TH * (float)m1), cosf(TH * (float)m2));
    }
    if (i < 130) g_win[i] = 0.5f - 0.5f * cosf(TH * (float)i);
}

__global__ void zero_out_k(float4* __restrict__ out, int n4) {
    int i = blockIdx.x * blockDim.x + threadIdx.x;
    float4 z = make_float4(0.f, 0.f, 0.f, 0.f);
    for (; i < n4; i += gridDim.x * blockDim.x) out[i] = z;
}

__device__ __forceinline__ float msig(float x) {
    float sg = 1.0f / (1.0f + __expf(-x));
    return 2.0f * __powf(sg, 2.302585092994046f) + 1e-7f;
}

// ---------------- wirb XOR swizzle (16B-chunk granularity): kills 6-way conflicts ----------------
__device__ __forceinline__ int swz_(int c) { return c ^ ((c >> 3) & 7); }
__device__ __forceinline__ ULL2 wld_(const float* wb, int c) {       // 16B load at chunk c
    return *(const ULL2*)(wb + (swz_(c) << 2));
}
__device__ __forceinline__ void wst_(float* wb, int i, float v) {    // scalar store at float idx i
    int c = i >> 2;
    wb[(swz_(c) << 2) | (i & 3)] = v;
}

// ---------------- dynamic smem layout (bytes) ----------------
#define SINTJ_OFF  0        // float[8][65][4] = 8320
#define XSB_OFF    8320     // float[8][4][64] = 8192
#define WIR_OFF    16512    // float[8][256]   = 8192 (swizzled; zero outside IR span)
#define OUTB_OFF   24704    // float[32][192]  = 24576
#define SMEM_TOT   49280    // 48.1 KB -> 4 CTAs/SM

__global__ __launch_bounds__(256, 4) void fn_main(
        const float* __restrict__ coeff,   // (B, F, 65)
        const float* __restrict__ noise,   // (B, F, 64)
        float* __restrict__ out)           // (B, 262144)
{
    extern __shared__ __align__(16) char smdyn[];
    float* sIntJ = (float*)(smdyn + SINTJ_OFF);   // [w][k][ff]
    float* xsb   = (float*)(smdyn + XSB_OFF);     // [w][ff][64]
    float* wirb  = (float*)(smdyn + WIR_OFF);     // [w][256] swizzled
    float* outb  = (float*)(smdyn + OUTB_OFF);    // [fi][192]

    const int tid = threadIdx.x;
    const int w   = tid >> 5;
    const int l   = tid & 31;
    const int q   = blockIdx.x;          // 0..127 (frames 0..4095; frame 4096 never contributes)
    const int b   = blockIdx.y;
    const int f0  = q * NFRB;

    // ---- stage inputs (msig / rescale), zero wir buffers ----
    for (int i = tid; i < NWARP * 256; i += 256) wirb[i] = 0.f;
    const size_t cbo = ((size_t)b * F_ + f0) * FCL_;
    for (int e = tid; e < NFRB * FCL_; e += 256) {
        int fi = e / 65, k = e - fi * 65;
        sIntJ[(((fi & 7) * 65) + k) * 4 + (fi >> 3)] = msig(coeff[cbo + e]);
    }
    const size_t nbo = ((size_t)b * F_ + f0) * FL_;
    for (int e = tid; e < NFRB * FL_; e += 256) {
        int fi = e >> 6, t = e & 63;
        xsb[((fi & 7) * 4 + (fi >> 3)) * 64 + t] = 2.f * noise[nbo + e] - 1.f;
    }
    __syncthreads();

    // ---- per-lane constants (L1-cached global) ----
    const int   t1  = l + 1,  t2 = l + 33;
    const float w1p = __ldg(&g_win[64 + t1]), w1m = __ldg(&g_win[64 - t1]);
    const float w2p = __ldg(&g_win[64 + t2]), w2m = __ldg(&g_win[64 - t2]);
    const float wc  = __ldg(&g_win[64]);
    float* wb = wirb + w * 256;

    // ---- cosine transform, 4 frames per warp jointly (packed f32x2) ----
    // zp[t] = (s0 + 2*sum_{k=1..64} s_k cos(2pi k t/129)) / 129 ; lane handles t1, t2
    const float* sw = sIntJ + w * 65 * 4;
    ull ac0AB = 0, ac0CD = 0, ac1AB = 0, ac1CD = 0, ac2AB = 0, ac2CD = 0;
    const ULL2 s0p = *(const ULL2*)sw;
    #pragma unroll 4
    for (int k = 1; k <= 64; k++) {
        const float2 ct = __ldg(&g_cosP[(k - 1) * 32 + l]);
        const ULL2 sp = *(const ULL2*)(sw + k * 4);   // broadcast LDS.128
        const ull c1d = dup_(ct.x), c2d = dup_(ct.y);
        ac1AB = fma2_(sp.x, c1d, ac1AB);  ac1CD = fma2_(sp.y, c1d, ac1CD);
        ac2AB = fma2_(sp.x, c2d, ac2AB);  ac2CD = fma2_(sp.y, c2d, ac2CD);
        ac0AB = add2_(ac0AB, sp.x);       ac0CD = add2_(ac0CD, sp.y);
    }
    const ull TWO = dup_(2.0f), SCL = dup_(1.0f / 129.0f);
    float zp0s[4], zp1s[4], zp2s[4];
    {
        ull r;
        r = mul2_(fma2_(ac0AB, TWO, s0p.x), SCL); unpk_(r, zp0s[0], zp0s[1]);
        r = mul2_(fma2_(ac0CD, TWO, s0p.y), SCL); unpk_(r, zp0s[2], zp0s[3]);
        r = mul2_(fma2_(ac1AB, TWO, s0p.x), SCL); unpk_(r, zp1s[0], zp1s[1]);
        r = mul2_(fma2_(ac1CD, TWO, s0p.y), SCL); unpk_(r, zp1s[2], zp1s[3]);
        r = mul2_(fma2_(ac2AB, TWO, s0p.x), SCL); unpk_(r, zp2s[0], zp2s[1]);
        r = mul2_(fma2_(ac2CD, TWO, s0p.y), SCL); unpk_(r, zp2s[2], zp2s[3]);
    }

    // ---- per-frame: windowed IR build + 64x192 linear conv ----
    #pragma unroll
    for (int ff = 0; ff < 4; ff++) {
        const int fi = ff * NWARP + w;

        // wb[128 +/- t] = win * zp (zp even-symmetric), swizzled stores
        wst_(wb, 128 + t1, w1p * zp1s[ff]);
        wst_(wb, 128 - t1, w1m * zp1s[ff]);
        wst_(wb, 128 + t2, w2p * zp2s[ff]);
        wst_(wb, 128 - t2, w2m * zp2s[ff]);
        if (l == 0) wst_(wb, 128, wc * zp0s[ff]);
        __syncwarp();

        // out[t] = sum_tau x[tau]*wb[64+t-tau], t = 8*ll + c (24 lanes x 8 outputs)
        const float* xs = xsb + (w * 4 + ff) * 64;
        const int ll = (l < 24) ? l : 0;
        const int cb = 15 + 2 * ll;          // chunk of float index 60 + 8*ll
        ull acc0 = 0, acc1 = 0, acc2 = 0, acc3 = 0;
        ULL2 va = wld_(wb, cb);
        ULL2 vb = wld_(wb, cb + 1);
        ULL2 vc = wld_(wb, cb + 2);
        ull E0 = va.x, E1 = va.y, E2 = vb.x, E3 = vb.y, E4 = vc.x, E5 = vc.y;
        float f0v, f1v, f2v, f3v, f4v, f5v, f6v, f7v, f8v, f9v, f10v, f11v;
        unpk_(E0, f0v, f1v); unpk_(E1, f2v, f3v); unpk_(E2, f4v, f5v);
        unpk_(E3, f6v, f7v); unpk_(E4, f8v, f9v); unpk_(E5, f10v, f11v);
        ull O0 = pk_(f1v, f2v), O1 = pk_(f3v, f4v), O2 = pk_(f5v, f6v);
        ull O3 = pk_(f7v, f8v), O4 = pk_(f9v, f10v);
        float carry = f0v;

        #pragma unroll
        for (int g = 0; g < 16; g++) {
            const float4 xq = *(const float4*)(xs + 4 * g);
            const ull x0 = dup_(xq.x), x1 = dup_(xq.y), x2 = dup_(xq.z), x3 = dup_(xq.w);
            acc0 = fma2_(x0, E2, acc0); acc1 = fma2_(x0, E3, acc1);
            acc2 = fma2_(x0, E4, acc2); acc3 = fma2_(x0, E5, acc3);
            acc0 = fma2_(x1, O1, acc0); acc1 = fma2_(x1, O2, acc1);
            acc2 = fma2_(x1, O3, acc2); acc3 = fma2_(x1, O4, acc3);
            acc0 = fma2_(x2, E1, acc0); acc1 = fma2_(x2, E2, acc1);
            acc2 = fma2_(x2, E3, acc2); acc3 = fma2_(x2, E4, acc3);
            acc0 = fma2_(x3, O0, acc0); acc1 = fma2_(x3, O1, acc1);
            acc2 = fma2_(x3, O2, acc2); acc3 = fma2_(x3, O3, acc3);
            if (g < 15) {
                const ULL2 nw = wld_(wb, cb - 1 - g);   // floats 56+8*ll-4g ..
                float nf0, nf1, nf2, nf3;
                unpk_(nw.x, nf0, nf1); unpk_(nw.y, nf2, nf3);
                E5 = E3; E4 = E2; E3 = E1; E2 = E0; E1 = nw.y; E0 = nw.x;
                O4 = O2; O3 = O1; O2 = O0; O1 = pk_(nf3, carry); O0 = pk_(nf1, nf2);
                carry = nf0;
            }
        }
        if (l < 24) {
            ULL2* op = (ULL2*)(outb + fi * 192 + 8 * l);
            op[0] = ULL2{acc0, acc1};
            op[1] = ULL2{acc2, acc3};
        }
        __syncwarp();   // wb reused by next frame
    }

    __syncthreads();

    // ---- overlap-add: interior exclusively owned, boundaries via atomics ----
    const size_t rowb = (size_t)b * OUT_S;
    const int gb = f0 * FL_;
    for (int p = tid; p < ACCLEN; p += 256) {
        const int P = gb + p;
        if (P >= OUT_S) continue;
        const int fhi = p >> 6;
        const int t0  = p & 63;
        float v = 0.f;
        if (fhi < NFRB)                 v += outb[fhi * 192 + t0];
        if (fhi >= 1 && fhi - 1 < NFRB) v += outb[(fhi - 1) * 192 + t0 + 64];
        if (fhi >= 2 && fhi - 2 < NFRB) v += outb[(fhi - 2) * 192 + t0 + 128];
        if (p >= 128 && p < 2048) out[rowb + P] = v;
        else                      atomicAdd(&out[rowb + P], v);
    }
}

extern "C" void kernel_launch(void* const* d_in, const int* in_sizes, int n_in,
                              void* d_out, int out_size) {
    const float* coeff = (const float*)d_in[0];
    const float* noise = (const float*)d_in[1];
    float* out = (float*)d_out;

    cudaFuncSetAttribute(fn_main, cudaFuncAttributeMaxDynamicSharedMemorySize, SMEM_TOT);
    init_tables_k<<<17, 128>>>();
    zero_out_k<<<4096, 256>>>((float4*)out, (B_ * OUT_S) / 4);
    dim3 grid(128, B_);
    fn_main<<<grid, 256, SMEM_TOT>>>(coeff, noise, out);
}

// round 7
// speedup vs baseline: 1.2608x; 1.0917x over previous
#include <cuda_runtime.h>
#include <math.h>

typedef unsigned long long ull;
struct __align__(16) ULL2 { ull x, y; };

#define B_     64
#define F_     4097
#define FCL_   65
#define FL_    64
#define OUT_S  262144
#define NFRB   32          // frames per block
#define NWARP  8
#define ACCLEN 2176        // (NFRB-1)*64 + 192

// ---------------- packed f32x2 helpers ----------------
__device__ __forceinline__ ull fma2_(ull a, ull b, ull c) {
    ull d; asm("fma.rn.f32x2 %0,%1,%2,%3;" : "=l"(d) : "l"(a), "l"(b), "l"(c)); return d;
}
__device__ __forceinline__ ull add2_(ull a, ull b) {
    ull d; asm("add.rn.f32x2 %0,%1,%2;" : "=l"(d) : "l"(a), "l"(b)); return d;
}
__device__ __forceinline__ ull mul2_(ull a, ull b) {
    ull d; asm("mul.rn.f32x2 %0,%1,%2;" : "=l"(d) : "l"(a), "l"(b)); return d;
}
__device__ __forceinline__ ull dup_(float x) {
    ull d; unsigned r = __float_as_uint(x);
    asm("mov.b64 %0,{%1,%1};" : "=l"(d) : "r"(r)); return d;
}
__device__ __forceinline__ ull pk_(float lo, float hi) {
    ull d; asm("mov.b64 %0,{%1,%2};" : "=l"(d) : "r"(__float_as_uint(lo)), "r"(__float_as_uint(hi))); return d;
}
__device__ __forceinline__ void unpk_(ull v, float& lo, float& hi) {
    unsigned a, b; asm("mov.b64 {%0,%1},%2;" : "=r"(a), "=r"(b) : "l"(v));
    lo = __uint_as_float(a); hi = __uint_as_float(b);
}

// ---------------- tables (L1-cached via __ldg; int mod-129 reduction) ----------------
__device__ float2 g_cosP[64 * 32];   // [k-1][l] = (cos(th*k*(l+1)), cos(th*k*(l+33)))
__device__ float  g_win[130];

// prep: build tables AND zero only the block-boundary strips of out
__global__ void prep_k(float4* __restrict__ out4) {
    const int i = blockIdx.x * blockDim.x + threadIdx.x;
    const float TH = 6.283185307179586477f / 129.0f;
    if (i < 64 * 32) {
        int k = (i >> 5) + 1, l = i & 31;
        int m1 = (k * (l + 1))  % 129;
        int m2 = (k * (l + 33)) % 129;
        g_cosP[i] = make_float2(cosf(TH * (float)m1), cosf(TH * (float)m2));
    }
    if (i < 130) g_win[i] = 0.5f - 0.5f * cosf(TH * (float)i);
    // zero out[b][q*2048 .. q*2048+128) for all b,q : 64*128*32 float4
    if (i < 64 * 128 * 32) {
        const int b  = i >> 12;
        const int r  = i & 4095;
        const int q  = r >> 5;
        const int j4 = r & 31;
        out4[b * 65536 + q * 512 + j4] = make_float4(0.f, 0.f, 0.f, 0.f);
    }
}

__device__ __forceinline__ float msig(float x) {
    float sg = 1.0f / (1.0f + __expf(-x));
    return 2.0f * __powf(sg, 2.302585092994046f) + 1e-7f;
}

// ---------------- wirb XOR swizzle (16B-chunk granularity) ----------------
__device__ __forceinline__ int swz_(int c) { return c ^ ((c >> 3) & 7); }
__device__ __forceinline__ ULL2 wld_(const float* wb, int c) {
    return *(const ULL2*)(wb + (swz_(c) << 2));
}
__device__ __forceinline__ void wst_(float* wb, int i, float v) {
    int c = i >> 2;
    wb[(swz_(c) << 2) | (i & 3)] = v;
}

// ---------------- dynamic smem layout (bytes) ----------------
#define SINTJ_OFF  0        // float[8][65][4] = 8320
#define WIR_OFF    8320     // float[8][256]   = 8192 (swizzled; zero outside IR span)
#define OUTB_OFF   16512    // float[32][192]  = 24576 (x staged in [fi][0..64) pre-conv)
#define SMEM_TOT   41088    // 40.1 KB -> 5 CTAs/SM

__global__ __launch_bounds__(256, 5) void fn_main(
        const float* __restrict__ coeff,   // (B, F, 65)
        const float* __restrict__ noise,   // (B, F, 64)
        float* __restrict__ out)           // (B, 262144)
{
    extern __shared__ __align__(16) char smdyn[];
    float* sIntJ = (float*)(smdyn + SINTJ_OFF);   // [w][k][ff]
    float* wirb  = (float*)(smdyn + WIR_OFF);     // [w][256] swizzled
    float* outb  = (float*)(smdyn + OUTB_OFF);    // [fi][192]

    const int tid = threadIdx.x;
    const int w   = tid >> 5;
    const int l   = tid & 31;
    const int q   = blockIdx.x;          // 0..127 (frames 0..4095; frame 4096 never contributes)
    const int b   = blockIdx.y;
    const int f0  = q * NFRB;

    // ---- stage inputs, zero wir buffers ----
    for (int i = tid; i < NWARP * 256; i += 256) wirb[i] = 0.f;
    const size_t cbo = ((size_t)b * F_ + f0) * FCL_;
    for (int e = tid; e < NFRB * FCL_; e += 256) {
        int fi = e / 65, k = e - fi * 65;
        sIntJ[(((fi & 7) * 65) + k) * 4 + (fi >> 3)] = msig(coeff[cbo + e]);
    }
    // x staged into the first 64 floats of each outb row (consumed before row write)
    const size_t nbo = ((size_t)b * F_ + f0) * FL_;
    for (int e = tid; e < NFRB * FL_; e += 256) {
        int fi = e >> 6, t = e & 63;
        outb[fi * 192 + t] = 2.f * noise[nbo + e] - 1.f;
    }
    __syncthreads();

    const int t1 = l + 1, t2 = l + 33;
    float* wb = wirb + w * 256;

    // ---- cosine transform, 4 frames per warp jointly (packed f32x2) ----
    // zp[t] = (s0 + 2*sum_{k=1..64} s_k cos(2pi k t/129)) / 129 ; lane handles t1, t2
    const float* sw = sIntJ + w * 65 * 4;
    ull ac0AB = 0, ac0CD = 0, ac1AB = 0, ac1CD = 0, ac2AB = 0, ac2CD = 0;
    const ULL2 s0p = *(const ULL2*)sw;
    #pragma unroll 4
    for (int k = 1; k <= 64; k++) {
        const float2 ct = __ldg(&g_cosP[(k - 1) * 32 + l]);
        const ULL2 sp = *(const ULL2*)(sw + k * 4);   // broadcast LDS.128
        const ull c1d = dup_(ct.x), c2d = dup_(ct.y);
        ac1AB = fma2_(sp.x, c1d, ac1AB);  ac1CD = fma2_(sp.y, c1d, ac1CD);
        ac2AB = fma2_(sp.x, c2d, ac2AB);  ac2CD = fma2_(sp.y, c2d, ac2CD);
        ac0AB = add2_(ac0AB, sp.x);       ac0CD = add2_(ac0CD, sp.y);
    }
    const ull TWO = dup_(2.0f), SCL = dup_(1.0f / 129.0f);
    float zp0s[4], zp1s[4], zp2s[4];
    {
        ull r;
        r = mul2_(fma2_(ac0AB, TWO, s0p.x), SCL); unpk_(r, zp0s[0], zp0s[1]);
        r = mul2_(fma2_(ac0CD, TWO, s0p.y), SCL); unpk_(r, zp0s[2], zp0s[3]);
        r = mul2_(fma2_(ac1AB, TWO, s0p.x), SCL); unpk_(r, zp1s[0], zp1s[1]);
        r = mul2_(fma2_(ac1CD, TWO, s0p.y), SCL); unpk_(r, zp1s[2], zp1s[3]);
        r = mul2_(fma2_(ac2AB, TWO, s0p.x), SCL); unpk_(r, zp2s[0], zp2s[1]);
        r = mul2_(fma2_(ac2CD, TWO, s0p.y), SCL); unpk_(r, zp2s[2], zp2s[3]);
    }

    // ---- per-frame: windowed IR build + 64x192 linear conv ----
    #pragma unroll
    for (int ff = 0; ff < 4; ff++) {
        const int fi = ff * NWARP + w;

        // wb[128 +/- t] = win * zp (zp even-symmetric); win via L1 (reg relief)
        wst_(wb, 128 + t1, __ldg(&g_win[64 + t1]) * zp1s[ff]);
        wst_(wb, 128 - t1, __ldg(&g_win[64 - t1]) * zp1s[ff]);
        wst_(wb, 128 + t2, __ldg(&g_win[64 + t2]) * zp2s[ff]);
        wst_(wb, 128 - t2, __ldg(&g_win[64 - t2]) * zp2s[ff]);
        if (l == 0) wst_(wb, 128, __ldg(&g_win[64]) * zp0s[ff]);
        __syncwarp();

        // out[t] = sum_tau x[tau]*wb[64+t-tau], t = 8*ll + c (24 lanes x 8 outputs)
        const float* xs = outb + fi * 192;     // staged x
        const int ll = (l < 24) ? l : 0;
        const int cb = 15 + 2 * ll;            // chunk of float index 60 + 8*ll
        ull acc0 = 0, acc1 = 0, acc2 = 0, acc3 = 0;
        ULL2 va = wld_(wb, cb);
        ULL2 vb = wld_(wb, cb + 1);
        ULL2 vc = wld_(wb, cb + 2);
        ull E0 = va.x, E1 = va.y, E2 = vb.x, E3 = vb.y, E4 = vc.x, E5 = vc.y;
        float f0v, f1v, f2v, f3v, f4v, f5v, f6v, f7v, f8v, f9v, f10v, f11v;
        unpk_(E0, f0v, f1v); unpk_(E1, f2v, f3v); unpk_(E2, f4v, f5v);
        unpk_(E3, f6v, f7v); unpk_(E4, f8v, f9v); unpk_(E5, f10v, f11v);
        ull O0 = pk_(f1v, f2v), O1 = pk_(f3v, f4v), O2 = pk_(f5v, f6v);
        ull O3 = pk_(f7v, f8v), O4 = pk_(f9v, f10v);
        float carry = f0v;

        #pragma unroll
        for (int g = 0; g < 16; g++) {
            const float4 xq = *(const float4*)(xs + 4 * g);
            const ull x0 = dup_(xq.x), x1 = dup_(xq.y), x2 = dup_(xq.z), x3 = dup_(xq.w);
            acc0 = fma2_(x0, E2, acc0); acc1 = fma2_(x0, E3, acc1);
            acc2 = fma2_(x0, E4, acc2); acc3 = fma2_(x0, E5, acc3);
            acc0 = fma2_(x1, O1, acc0); acc1 = fma2_(x1, O2, acc1);
            acc2 = fma2_(x1, O3, acc2); acc3 = fma2_(x1, O4, acc3);
            acc0 = fma2_(x2, E1, acc0); acc1 = fma2_(x2, E2, acc1);
            acc2 = fma2_(x2, E3, acc2); acc3 = fma2_(x2, E4, acc3);
            acc0 = fma2_(x3, O0, acc0); acc1 = fma2_(x3, O1, acc1);
            acc2 = fma2_(x3, O2, acc2); acc3 = fma2_(x3, O3, acc3);
            if (g < 15) {
                const ULL2 nw = wld_(wb, cb - 1 - g);
                float nf0, nf1, nf2, nf3;
                unpk_(nw.x, nf0, nf1); unpk_(nw.y, nf2, nf3);
                E5 = E3; E4 = E2; E3 = E1; E2 = E0; E1 = nw.y; E0 = nw.x;
                O4 = O2; O3 = O1; O2 = O0; O1 = pk_(nf3, carry); O0 = pk_(nf1, nf2);
                carry = nf0;
            }
        }
        __syncwarp();   // all lanes' x reads done before the row is overwritten
        if (l < 24) {
            ULL2* op = (ULL2*)(outb + fi * 192 + 8 * l);
            op[0] = ULL2{acc0, acc1};
            op[1] = ULL2{acc2, acc3};
        }
        __syncwarp();   // wb/row settled before next frame
    }

    __syncthreads();

    // ---- overlap-add: interior exclusively owned, boundaries via atomics ----
    const size_t rowb = (size_t)b * OUT_S;
    const int gb = f0 * FL_;
    for (int p = tid; p < ACCLEN; p += 256) {
        const int P = gb + p;
        if (P >= OUT_S) continue;
        const int fhi = p >> 6;
        const int t0  = p & 63;
        float v = 0.f;
        if (fhi < NFRB)                 v += outb[fhi * 192 + t0];
        if (fhi >= 1 && fhi - 1 < NFRB) v += outb[(fhi - 1) * 192 + t0 + 64];
        if (fhi >= 2 && fhi - 2 < NFRB) v += outb[(fhi - 2) * 192 + t0 + 128];
        if (p >= 128 && p < 2048) out[rowb + P] = v;
        else                      atomicAdd(&out[rowb + P], v);
    }
}

extern "C" void kernel_launch(void* const* d_in, const int* in_sizes, int n_in,
                              void* d_out, int out_size) {
    const float* coeff = (const float*)d_in[0];
    const float* noise = (const float*)d_in[1];
    float* out = (float*)d_out;

    cudaFuncSetAttribute(fn_main, cudaFuncAttributeMaxDynamicSharedMemorySize, SMEM_TOT);
    prep_k<<<1024, 256>>>((float4*)out);
    dim3 grid(128, B_);
    fn_main<<<grid, 256, SMEM_TOT>>>(coeff, noise, out);
}